// round 15
// baseline (speedup 1.0000x reference)
#include <cuda_runtime.h>
#include <math.h>
#include <stdint.h>

#define DIM   64
#define WARPS 8
#define BATCH 4
#define MAXN  65537
#define FULL  0xffffffffu

// packed {log2(e), log2(e)}
#define L2E2  0x3FB8AA3B3FB8AA3Bull

// Scratch (device globals — no allocations allowed)
__device__ int   g_row_ptr[MAXN + 1];
__device__ float g_Wt[DIM * DIM];   // Wt[k*64 + j] = W[j*64 + k]
__device__ int   g_ctr;

// ---------------------------------------------------------------------------
// Prep: W transpose + CSR row_ptr from SORTED dst (int4 loads) + ticket reset.
// ---------------------------------------------------------------------------
__global__ void prep_kernel(const int* __restrict__ dst,
                            const float* __restrict__ W, int E, int N) {
    const int t = blockIdx.x * blockDim.x + threadIdx.x;
    if (t == 0) g_ctr = 0;
    if (t < DIM * DIM) {
        const int j = t & (DIM - 1);
        const int k = t >> 6;
        g_Wt[t] = W[j * DIM + k];
    }
    const int e4 = t * 4;
    if (e4 >= E) return;
    if (e4 + 3 < E) {
        const int4 d = reinterpret_cast<const int4*>(dst)[t];
        const int dm1 = (e4 == 0) ? -1 : __ldg(&dst[e4 - 1]);
        for (int j = dm1 + 1;  j <= d.x; ++j) g_row_ptr[j] = e4;
        for (int j = d.x + 1;  j <= d.y; ++j) g_row_ptr[j] = e4 + 1;
        for (int j = d.y + 1;  j <= d.z; ++j) g_row_ptr[j] = e4 + 2;
        for (int j = d.z + 1;  j <= d.w; ++j) g_row_ptr[j] = e4 + 3;
        if (e4 + 4 >= E)
            for (int j = d.w + 1; j <= N; ++j) g_row_ptr[j] = E;
    } else {
        for (int e = e4; e < E; ++e) {
            const int d     = dst[e];
            const int dprev = (e == 0) ? -1 : dst[e - 1];
            for (int j = dprev + 1; j <= d; ++j) g_row_ptr[j] = e;
            if (e == E - 1)
                for (int j = d + 1; j <= N; ++j) g_row_ptr[j] = E;
        }
    }
}

// ---------------------------------------------------------------------------
// Fused kernel v9 — R13 (best: 64.0us) with the occupancy trade:
//   * in-flight window 8 -> 6 edges (3 per half-warp): -8 regs of load data.
//     R11 timing showed effective MLP ~2, so the textual window is not
//     realized anyway; cutting it should cost little.
//   * __launch_bounds__(256, 5): 5 blocks/SM -> 40 warps (+25% issue and
//     latency-hiding capacity). Chip in-flight 40x6 ~= 32x8 (neutral).
// Everything else identical to R13: warp-per-node ticketed BATCH=4,
// coalesced warp-wide src chunk + shfl, ef streamed via __ldcs, packed
// f32x2 edge math, softmax without max-shift (m ~ N(0,2), |m| < ~9 over
// 5e7 samples -> exp < 8.2e3; shift cancels exactly), __fdividef
// normalize, BATCH-amortized MLP.
// ---------------------------------------------------------------------------
__global__ void __launch_bounds__(WARPS * 32, 5)
fused_kernel(const float4* __restrict__ nf4,
             const float4* __restrict__ ef4,
             const int*    __restrict__ src,
             const float*  __restrict__ nf,
             const float*  __restrict__ bias,
             float*        __restrict__ out,
             int N) {
    const int w    = threadIdx.x >> 5;
    const int lane = threadIdx.x & 31;
    const int half = lane >> 4;
    const int l4   = lane & 15;

    __shared__ float4 s_agg[WARPS][BATCH][16];   // 8KB

    const float2* __restrict__ Wt2 = reinterpret_cast<const float2*>(g_Wt);
    const float2  bb = reinterpret_cast<const float2*>(bias)[lane];

    int t = 0;
    if (lane == 0) t = atomicAdd(&g_ctr, BATCH);
    int base = __shfl_sync(FULL, t, 0);

    while (base < N) {
        if (lane == 0) t = atomicAdd(&g_ctr, BATCH);   // prefetch next ticket
        const int nxt = __shfl_sync(FULL, t, 0);

        // ---- Phase A: aggregate BATCH nodes ----
        for (int q = 0; q < BATCH; ++q) {
            const int v = base + q;
            int lo = 0, hi = 0;
            if (v < N) { lo = g_row_ptr[v]; hi = g_row_ptr[v + 1]; }

            // packed accumulators: {s0,s1},{s2,s3},{ws0,ws1},{ws2,ws3}
            uint64_t s01 = 0ull, s23 = 0ull, ws01 = 0ull, ws23 = 0ull;

// packed-f32x2 edge math (R13 win): 2 ADD2 + 2 MUL2 + 4 EX2 + 2 ADD2 + 2 FMA2
#define EDGE_MATH(a, b) do {                                                   \
    uint64_t a01, a23, b01, b23, m01, m23, t01, t23, e01, e23;                 \
    asm("mov.b64 %0, {%1,%2};" : "=l"(a01) : "f"((a).x), "f"((a).y));          \
    asm("mov.b64 %0, {%1,%2};" : "=l"(a23) : "f"((a).z), "f"((a).w));          \
    asm("mov.b64 %0, {%1,%2};" : "=l"(b01) : "f"((b).x), "f"((b).y));          \
    asm("mov.b64 %0, {%1,%2};" : "=l"(b23) : "f"((b).z), "f"((b).w));          \
    asm("add.rn.f32x2 %0, %1, %2;" : "=l"(m01) : "l"(a01), "l"(b01));          \
    asm("add.rn.f32x2 %0, %1, %2;" : "=l"(m23) : "l"(a23), "l"(b23));          \
    asm("mul.rn.f32x2 %0, %1, %2;" : "=l"(t01) : "l"(m01), "l"(L2E2));         \
    asm("mul.rn.f32x2 %0, %1, %2;" : "=l"(t23) : "l"(m23), "l"(L2E2));         \
    float t0, t1, t2, t3, e0, e1, e2, e3;                                      \
    asm("mov.b64 {%0,%1}, %2;" : "=f"(t0), "=f"(t1) : "l"(t01));               \
    asm("mov.b64 {%0,%1}, %2;" : "=f"(t2), "=f"(t3) : "l"(t23));               \
    asm("ex2.approx.f32 %0, %1;" : "=f"(e0) : "f"(t0));                        \
    asm("ex2.approx.f32 %0, %1;" : "=f"(e1) : "f"(t1));                        \
    asm("ex2.approx.f32 %0, %1;" : "=f"(e2) : "f"(t2));                        \
    asm("ex2.approx.f32 %0, %1;" : "=f"(e3) : "f"(t3));                        \
    asm("mov.b64 %0, {%1,%2};" : "=l"(e01) : "f"(e0), "f"(e1));                \
    asm("mov.b64 %0, {%1,%2};" : "=l"(e23) : "f"(e2), "f"(e3));                \
    asm("add.rn.f32x2 %0, %0, %1;" : "+l"(s01) : "l"(e01));                    \
    asm("add.rn.f32x2 %0, %0, %1;" : "+l"(s23) : "l"(e23));                    \
    asm("fma.rn.f32x2 %0, %1, %2, %0;" : "+l"(ws01) : "l"(m01), "l"(e01));     \
    asm("fma.rn.f32x2 %0, %1, %2, %0;" : "+l"(ws23) : "l"(m23), "l"(e23));     \
} while (0)

            for (int cb = lo; cb < hi; cb += 32) {
                const int cnt = min(32, hi - cb);
                const int su = __ldg(&src[cb + min(lane, cnt - 1)]);

                int i = 0;
                for (; i + 6 <= cnt; i += 6) {          // 6 edges in flight
                    const int ib = i + 3 * half;        // this half's 3 edges
                    const int u0 = __shfl_sync(FULL, su, ib + 0);
                    const int u1 = __shfl_sync(FULL, su, ib + 1);
                    const int u2 = __shfl_sync(FULL, su, ib + 2);
                    const unsigned eb = (unsigned)(cb + ib) * 16u + l4;
                    const float4 a0 = __ldg (&nf4[(unsigned)u0 * 16u + l4]);
                    const float4 b0 = __ldcs(&ef4[eb +  0]);
                    const float4 a1 = __ldg (&nf4[(unsigned)u1 * 16u + l4]);
                    const float4 b1 = __ldcs(&ef4[eb + 16]);
                    const float4 a2 = __ldg (&nf4[(unsigned)u2 * 16u + l4]);
                    const float4 b2 = __ldcs(&ef4[eb + 32]);
                    EDGE_MATH(a0, b0);
                    EDGE_MATH(a1, b1);
                    EDGE_MATH(a2, b2);
                }
                for (; i + 2 <= cnt; i += 2) {          // 2-edge remainder
                    const int u = __shfl_sync(FULL, su, i + half);
                    const float4 a = __ldg (&nf4[(unsigned)u * 16u + l4]);
                    const float4 b = __ldcs(&ef4[(unsigned)(cb + i + half) * 16u + l4]);
                    EDGE_MATH(a, b);
                }
                if (i < cnt) {                          // last odd edge
                    const int u = __shfl_sync(FULL, su, i);
                    if (half == 0) {
                        const float4 a = __ldg (&nf4[(unsigned)u * 16u + l4]);
                        const float4 b = __ldcs(&ef4[(unsigned)(cb + i) * 16u + l4]);
                        EDGE_MATH(a, b);
                    }
                }
            }
#undef EDGE_MATH

            // unpack accumulators, combine half-warps
            float4 s, ws;
            asm("mov.b64 {%0,%1}, %2;" : "=f"(s.x),  "=f"(s.y)  : "l"(s01));
            asm("mov.b64 {%0,%1}, %2;" : "=f"(s.z),  "=f"(s.w)  : "l"(s23));
            asm("mov.b64 {%0,%1}, %2;" : "=f"(ws.x), "=f"(ws.y) : "l"(ws01));
            asm("mov.b64 {%0,%1}, %2;" : "=f"(ws.z), "=f"(ws.w) : "l"(ws23));

            s.x  += __shfl_down_sync(FULL, s.x,  16);
            s.y  += __shfl_down_sync(FULL, s.y,  16);
            s.z  += __shfl_down_sync(FULL, s.z,  16);
            s.w  += __shfl_down_sync(FULL, s.w,  16);
            ws.x += __shfl_down_sync(FULL, ws.x, 16);
            ws.y += __shfl_down_sync(FULL, ws.y, 16);
            ws.z += __shfl_down_sync(FULL, ws.z, 16);
            ws.w += __shfl_down_sync(FULL, ws.w, 16);

            if (half == 0) {
                float4 agg = make_float4(0.f, 0.f, 0.f, 0.f);
                if (hi > lo) {
                    agg.x = __fdividef(ws.x, fmaxf(s.x, 1e-38f));
                    agg.y = __fdividef(ws.y, fmaxf(s.y, 1e-38f));
                    agg.z = __fdividef(ws.z, fmaxf(s.z, 1e-38f));
                    agg.w = __fdividef(ws.w, fmaxf(s.w, 1e-38f));
                }
                s_agg[w][q][l4] = agg;
            }
        }
        __syncwarp();

        // ---- Phase B: one MLP pass for BATCH nodes (W amortized 4x) ----
        float2 acc0 = make_float2(0.f, 0.f), acc1 = make_float2(0.f, 0.f);
        float2 acc2 = make_float2(0.f, 0.f), acc3 = make_float2(0.f, 0.f);
        for (int k4 = 0; k4 < 16; ++k4) {
            const float2 wv0 = Wt2[(4 * k4 + 0) * 32 + lane];
            const float2 wv1 = Wt2[(4 * k4 + 1) * 32 + lane];
            const float2 wv2 = Wt2[(4 * k4 + 2) * 32 + lane];
            const float2 wv3 = Wt2[(4 * k4 + 3) * 32 + lane];
            const float4 a0 = s_agg[w][0][k4];   // broadcast LDS.128
            const float4 a1 = s_agg[w][1][k4];
            const float4 a2 = s_agg[w][2][k4];
            const float4 a3 = s_agg[w][3][k4];
            acc0.x = fmaf(a0.x, wv0.x, acc0.x); acc0.y = fmaf(a0.x, wv0.y, acc0.y);
            acc0.x = fmaf(a0.y, wv1.x, acc0.x); acc0.y = fmaf(a0.y, wv1.y, acc0.y);
            acc0.x = fmaf(a0.z, wv2.x, acc0.x); acc0.y = fmaf(a0.z, wv2.y, acc0.y);
            acc0.x = fmaf(a0.w, wv3.x, acc0.x); acc0.y = fmaf(a0.w, wv3.y, acc0.y);
            acc1.x = fmaf(a1.x, wv0.x, acc1.x); acc1.y = fmaf(a1.x, wv0.y, acc1.y);
            acc1.x = fmaf(a1.y, wv1.x, acc1.x); acc1.y = fmaf(a1.y, wv1.y, acc1.y);
            acc1.x = fmaf(a1.z, wv2.x, acc1.x); acc1.y = fmaf(a1.z, wv2.y, acc1.y);
            acc1.x = fmaf(a1.w, wv3.x, acc1.x); acc1.y = fmaf(a1.w, wv3.y, acc1.y);
            acc2.x = fmaf(a2.x, wv0.x, acc2.x); acc2.y = fmaf(a2.x, wv0.y, acc2.y);
            acc2.x = fmaf(a2.y, wv1.x, acc2.x); acc2.y = fmaf(a2.y, wv1.y, acc2.y);
            acc2.x = fmaf(a2.z, wv2.x, acc2.x); acc2.y = fmaf(a2.z, wv2.y, acc2.y);
            acc2.x = fmaf(a2.w, wv3.x, acc2.x); acc2.y = fmaf(a2.w, wv3.y, acc2.y);
            acc3.x = fmaf(a3.x, wv0.x, acc3.x); acc3.y = fmaf(a3.x, wv0.y, acc3.y);
            acc3.x = fmaf(a3.y, wv1.x, acc3.x); acc3.y = fmaf(a3.y, wv1.y, acc3.y);
            acc3.x = fmaf(a3.z, wv2.x, acc3.x); acc3.y = fmaf(a3.z, wv2.y, acc3.y);
            acc3.x = fmaf(a3.w, wv3.x, acc3.x); acc3.y = fmaf(a3.w, wv3.y, acc3.y);
        }

        const float2 accs[BATCH] = {acc0, acc1, acc2, acc3};
#pragma unroll
        for (int q = 0; q < BATCH; ++q) {
            const int v = base + q;
            if (v < N) {
                const float2 res =
                    reinterpret_cast<const float2*>(nf)[(size_t)v * 32 + lane];
                float2 o;
                o.x = fmaxf(accs[q].x + bb.x, 0.f) + res.x;
                o.y = fmaxf(accs[q].y + bb.y, 0.f) + res.y;
                reinterpret_cast<float2*>(out)[(size_t)v * 32 + lane] = o;
            }
        }
        __syncwarp();
        base = nxt;
    }
}

// ---------------------------------------------------------------------------
// Input order: node_feats, edge_feats, src, dst, W, b
// ---------------------------------------------------------------------------
extern "C" void kernel_launch(void* const* d_in, const int* in_sizes, int n_in,
                              void* d_out, int out_size) {
    const float* nf  = (const float*)d_in[0];
    const float* ef  = (const float*)d_in[1];
    const int*   src = (const int*)  d_in[2];
    const int*   dst = (const int*)  d_in[3];
    const float* W   = (const float*)d_in[4];
    const float* b   = (const float*)d_in[5];
    float* out = (float*)d_out;

    const int N = in_sizes[0] / DIM;
    const int E = in_sizes[2];

    const int prep_threads = (E + 3) / 4;
    prep_kernel<<<(prep_threads + 255) / 256, 256>>>(dst, W, E, N);
    fused_kernel<<<148 * 10, WARPS * 32>>>(
        (const float4*)nf, (const float4*)ef, src, nf, b, out, N);
}

// round 16
// speedup vs baseline: 1.0443x; 1.0443x over previous
#include <cuda_runtime.h>
#include <math.h>
#include <stdint.h>

#define DIM   64
#define WARPS 8
#define BATCH 4
#define MAXN  65537
#define FULL  0xffffffffu

// packed {log2(e), log2(e)}
#define L2E2  0x3FB8AA3B3FB8AA3Bull

// Scratch (device globals — no allocations allowed)
__device__ int   g_row_ptr[MAXN + 1];
__device__ float g_Wt[DIM * DIM];   // Wt[k*64 + j] = W[j*64 + k]
__device__ int   g_ctr;

// ---------------------------------------------------------------------------
// Prep: W transpose + CSR row_ptr from SORTED dst (int4 loads) + ticket reset.
// ---------------------------------------------------------------------------
__global__ void prep_kernel(const int* __restrict__ dst,
                            const float* __restrict__ W, int E, int N) {
    const int t = blockIdx.x * blockDim.x + threadIdx.x;
    if (t == 0) g_ctr = 0;
    if (t < DIM * DIM) {
        const int j = t & (DIM - 1);
        const int k = t >> 6;
        g_Wt[t] = W[j * DIM + k];
    }
    const int e4 = t * 4;
    if (e4 >= E) return;
    if (e4 + 3 < E) {
        const int4 d = reinterpret_cast<const int4*>(dst)[t];
        const int dm1 = (e4 == 0) ? -1 : __ldg(&dst[e4 - 1]);
        for (int j = dm1 + 1;  j <= d.x; ++j) g_row_ptr[j] = e4;
        for (int j = d.x + 1;  j <= d.y; ++j) g_row_ptr[j] = e4 + 1;
        for (int j = d.y + 1;  j <= d.z; ++j) g_row_ptr[j] = e4 + 2;
        for (int j = d.z + 1;  j <= d.w; ++j) g_row_ptr[j] = e4 + 3;
        if (e4 + 4 >= E)
            for (int j = d.w + 1; j <= N; ++j) g_row_ptr[j] = E;
    } else {
        for (int e = e4; e < E; ++e) {
            const int d     = dst[e];
            const int dprev = (e == 0) ? -1 : dst[e - 1];
            for (int j = dprev + 1; j <= d; ++j) g_row_ptr[j] = e;
            if (e == E - 1)
                for (int j = d + 1; j <= N; ++j) g_row_ptr[j] = E;
        }
    }
}

// ---------------------------------------------------------------------------
// Fused kernel v10 — R13 (best: 64.0us) with the window trade INVERTED.
//
// R14 evidence: window 8->6 with +25% warps REGRESSED 18% (occ up, DRAM
// down) -> per-warp in-flight window is the binding resource; warp count is
// weakly negative. So: window 8 -> 12 edges (6 per half-warp, 48 regs of
// load data), paid for with __launch_bounds__(256, 3) (~85-reg budget).
// Chip in-flight: 24 warps x 12 = 288 vs 32 x 8 = 256, and each warp's
// dependent stream is 50% deeper.
//
// Everything else identical to R13: warp-per-node ticketed BATCH=4,
// coalesced warp-wide src chunk + shfl, ef streamed via __ldcs, packed
// f32x2 edge math, softmax without max-shift (m ~ N(0,2), |m| < ~9 over
// 5e7 samples -> exp < 8.2e3; shift cancels exactly), __fdividef
// normalize, BATCH-amortized MLP.
// ---------------------------------------------------------------------------
__global__ void __launch_bounds__(WARPS * 32, 3)
fused_kernel(const float4* __restrict__ nf4,
             const float4* __restrict__ ef4,
             const int*    __restrict__ src,
             const float*  __restrict__ nf,
             const float*  __restrict__ bias,
             float*        __restrict__ out,
             int N) {
    const int w    = threadIdx.x >> 5;
    const int lane = threadIdx.x & 31;
    const int half = lane >> 4;
    const int l4   = lane & 15;

    __shared__ float4 s_agg[WARPS][BATCH][16];   // 8KB

    const float2* __restrict__ Wt2 = reinterpret_cast<const float2*>(g_Wt);
    const float2  bb = reinterpret_cast<const float2*>(bias)[lane];

    int t = 0;
    if (lane == 0) t = atomicAdd(&g_ctr, BATCH);
    int base = __shfl_sync(FULL, t, 0);

    while (base < N) {
        if (lane == 0) t = atomicAdd(&g_ctr, BATCH);   // prefetch next ticket
        const int nxt = __shfl_sync(FULL, t, 0);

        // ---- Phase A: aggregate BATCH nodes ----
        for (int q = 0; q < BATCH; ++q) {
            const int v = base + q;
            int lo = 0, hi = 0;
            if (v < N) { lo = g_row_ptr[v]; hi = g_row_ptr[v + 1]; }

            // packed accumulators: {s0,s1},{s2,s3},{ws0,ws1},{ws2,ws3}
            uint64_t s01 = 0ull, s23 = 0ull, ws01 = 0ull, ws23 = 0ull;

// packed-f32x2 edge math (R13 win): 2 ADD2 + 2 MUL2 + 4 EX2 + 2 ADD2 + 2 FMA2
#define EDGE_MATH(a, b) do {                                                   \
    uint64_t a01, a23, b01, b23, m01, m23, t01, t23, e01, e23;                 \
    asm("mov.b64 %0, {%1,%2};" : "=l"(a01) : "f"((a).x), "f"((a).y));          \
    asm("mov.b64 %0, {%1,%2};" : "=l"(a23) : "f"((a).z), "f"((a).w));          \
    asm("mov.b64 %0, {%1,%2};" : "=l"(b01) : "f"((b).x), "f"((b).y));          \
    asm("mov.b64 %0, {%1,%2};" : "=l"(b23) : "f"((b).z), "f"((b).w));          \
    asm("add.rn.f32x2 %0, %1, %2;" : "=l"(m01) : "l"(a01), "l"(b01));          \
    asm("add.rn.f32x2 %0, %1, %2;" : "=l"(m23) : "l"(a23), "l"(b23));          \
    asm("mul.rn.f32x2 %0, %1, %2;" : "=l"(t01) : "l"(m01), "l"(L2E2));         \
    asm("mul.rn.f32x2 %0, %1, %2;" : "=l"(t23) : "l"(m23), "l"(L2E2));         \
    float t0, t1, t2, t3, e0, e1, e2, e3;                                      \
    asm("mov.b64 {%0,%1}, %2;" : "=f"(t0), "=f"(t1) : "l"(t01));               \
    asm("mov.b64 {%0,%1}, %2;" : "=f"(t2), "=f"(t3) : "l"(t23));               \
    asm("ex2.approx.f32 %0, %1;" : "=f"(e0) : "f"(t0));                        \
    asm("ex2.approx.f32 %0, %1;" : "=f"(e1) : "f"(t1));                        \
    asm("ex2.approx.f32 %0, %1;" : "=f"(e2) : "f"(t2));                        \
    asm("ex2.approx.f32 %0, %1;" : "=f"(e3) : "f"(t3));                        \
    asm("mov.b64 %0, {%1,%2};" : "=l"(e01) : "f"(e0), "f"(e1));                \
    asm("mov.b64 %0, {%1,%2};" : "=l"(e23) : "f"(e2), "f"(e3));                \
    asm("add.rn.f32x2 %0, %0, %1;" : "+l"(s01) : "l"(e01));                    \
    asm("add.rn.f32x2 %0, %0, %1;" : "+l"(s23) : "l"(e23));                    \
    asm("fma.rn.f32x2 %0, %1, %2, %0;" : "+l"(ws01) : "l"(m01), "l"(e01));     \
    asm("fma.rn.f32x2 %0, %1, %2, %0;" : "+l"(ws23) : "l"(m23), "l"(e23));     \
} while (0)

            for (int cb = lo; cb < hi; cb += 32) {
                const int cnt = min(32, hi - cb);
                const int su = __ldg(&src[cb + min(lane, cnt - 1)]);

                int i = 0;
                for (; i + 12 <= cnt; i += 12) {        // 12 edges in flight
                    const int ib = i + 6 * half;        // this half's 6 edges
                    const int u0 = __shfl_sync(FULL, su, ib + 0);
                    const int u1 = __shfl_sync(FULL, su, ib + 1);
                    const int u2 = __shfl_sync(FULL, su, ib + 2);
                    const int u3 = __shfl_sync(FULL, su, ib + 3);
                    const int u4 = __shfl_sync(FULL, su, ib + 4);
                    const int u5 = __shfl_sync(FULL, su, ib + 5);
                    const unsigned eb = (unsigned)(cb + ib) * 16u + l4;
                    const float4 a0 = __ldg (&nf4[(unsigned)u0 * 16u + l4]);
                    const float4 b0 = __ldcs(&ef4[eb +  0]);
                    const float4 a1 = __ldg (&nf4[(unsigned)u1 * 16u + l4]);
                    const float4 b1 = __ldcs(&ef4[eb + 16]);
                    const float4 a2 = __ldg (&nf4[(unsigned)u2 * 16u + l4]);
                    const float4 b2 = __ldcs(&ef4[eb + 32]);
                    const float4 a3 = __ldg (&nf4[(unsigned)u3 * 16u + l4]);
                    const float4 b3 = __ldcs(&ef4[eb + 48]);
                    const float4 a4 = __ldg (&nf4[(unsigned)u4 * 16u + l4]);
                    const float4 b4 = __ldcs(&ef4[eb + 64]);
                    const float4 a5 = __ldg (&nf4[(unsigned)u5 * 16u + l4]);
                    const float4 b5 = __ldcs(&ef4[eb + 80]);
                    EDGE_MATH(a0, b0);
                    EDGE_MATH(a1, b1);
                    EDGE_MATH(a2, b2);
                    EDGE_MATH(a3, b3);
                    EDGE_MATH(a4, b4);
                    EDGE_MATH(a5, b5);
                }
                for (; i + 2 <= cnt; i += 2) {          // 2-edge remainder
                    const int u = __shfl_sync(FULL, su, i + half);
                    const float4 a = __ldg (&nf4[(unsigned)u * 16u + l4]);
                    const float4 b = __ldcs(&ef4[(unsigned)(cb + i + half) * 16u + l4]);
                    EDGE_MATH(a, b);
                }
                if (i < cnt) {                          // last odd edge
                    const int u = __shfl_sync(FULL, su, i);
                    if (half == 0) {
                        const float4 a = __ldg (&nf4[(unsigned)u * 16u + l4]);
                        const float4 b = __ldcs(&ef4[(unsigned)(cb + i) * 16u + l4]);
                        EDGE_MATH(a, b);
                    }
                }
            }
#undef EDGE_MATH

            // unpack accumulators, combine half-warps
            float4 s, ws;
            asm("mov.b64 {%0,%1}, %2;" : "=f"(s.x),  "=f"(s.y)  : "l"(s01));
            asm("mov.b64 {%0,%1}, %2;" : "=f"(s.z),  "=f"(s.w)  : "l"(s23));
            asm("mov.b64 {%0,%1}, %2;" : "=f"(ws.x), "=f"(ws.y) : "l"(ws01));
            asm("mov.b64 {%0,%1}, %2;" : "=f"(ws.z), "=f"(ws.w) : "l"(ws23));

            s.x  += __shfl_down_sync(FULL, s.x,  16);
            s.y  += __shfl_down_sync(FULL, s.y,  16);
            s.z  += __shfl_down_sync(FULL, s.z,  16);
            s.w  += __shfl_down_sync(FULL, s.w,  16);
            ws.x += __shfl_down_sync(FULL, ws.x, 16);
            ws.y += __shfl_down_sync(FULL, ws.y, 16);
            ws.z += __shfl_down_sync(FULL, ws.z, 16);
            ws.w += __shfl_down_sync(FULL, ws.w, 16);

            if (half == 0) {
                float4 agg = make_float4(0.f, 0.f, 0.f, 0.f);
                if (hi > lo) {
                    agg.x = __fdividef(ws.x, fmaxf(s.x, 1e-38f));
                    agg.y = __fdividef(ws.y, fmaxf(s.y, 1e-38f));
                    agg.z = __fdividef(ws.z, fmaxf(s.z, 1e-38f));
                    agg.w = __fdividef(ws.w, fmaxf(s.w, 1e-38f));
                }
                s_agg[w][q][l4] = agg;
            }
        }
        __syncwarp();

        // ---- Phase B: one MLP pass for BATCH nodes (W amortized 4x) ----
        float2 acc0 = make_float2(0.f, 0.f), acc1 = make_float2(0.f, 0.f);
        float2 acc2 = make_float2(0.f, 0.f), acc3 = make_float2(0.f, 0.f);
        for (int k4 = 0; k4 < 16; ++k4) {
            const float2 wv0 = Wt2[(4 * k4 + 0) * 32 + lane];
            const float2 wv1 = Wt2[(4 * k4 + 1) * 32 + lane];
            const float2 wv2 = Wt2[(4 * k4 + 2) * 32 + lane];
            const float2 wv3 = Wt2[(4 * k4 + 3) * 32 + lane];
            const float4 a0 = s_agg[w][0][k4];   // broadcast LDS.128
            const float4 a1 = s_agg[w][1][k4];
            const float4 a2 = s_agg[w][2][k4];
            const float4 a3 = s_agg[w][3][k4];
            acc0.x = fmaf(a0.x, wv0.x, acc0.x); acc0.y = fmaf(a0.x, wv0.y, acc0.y);
            acc0.x = fmaf(a0.y, wv1.x, acc0.x); acc0.y = fmaf(a0.y, wv1.y, acc0.y);
            acc0.x = fmaf(a0.z, wv2.x, acc0.x); acc0.y = fmaf(a0.z, wv2.y, acc0.y);
            acc0.x = fmaf(a0.w, wv3.x, acc0.x); acc0.y = fmaf(a0.w, wv3.y, acc0.y);
            acc1.x = fmaf(a1.x, wv0.x, acc1.x); acc1.y = fmaf(a1.x, wv0.y, acc1.y);
            acc1.x = fmaf(a1.y, wv1.x, acc1.x); acc1.y = fmaf(a1.y, wv1.y, acc1.y);
            acc1.x = fmaf(a1.z, wv2.x, acc1.x); acc1.y = fmaf(a1.z, wv2.y, acc1.y);
            acc1.x = fmaf(a1.w, wv3.x, acc1.x); acc1.y = fmaf(a1.w, wv3.y, acc1.y);
            acc2.x = fmaf(a2.x, wv0.x, acc2.x); acc2.y = fmaf(a2.x, wv0.y, acc2.y);
            acc2.x = fmaf(a2.y, wv1.x, acc2.x); acc2.y = fmaf(a2.y, wv1.y, acc2.y);
            acc2.x = fmaf(a2.z, wv2.x, acc2.x); acc2.y = fmaf(a2.z, wv2.y, acc2.y);
            acc2.x = fmaf(a2.w, wv3.x, acc2.x); acc2.y = fmaf(a2.w, wv3.y, acc2.y);
            acc3.x = fmaf(a3.x, wv0.x, acc3.x); acc3.y = fmaf(a3.x, wv0.y, acc3.y);
            acc3.x = fmaf(a3.y, wv1.x, acc3.x); acc3.y = fmaf(a3.y, wv1.y, acc3.y);
            acc3.x = fmaf(a3.z, wv2.x, acc3.x); acc3.y = fmaf(a3.z, wv2.y, acc3.y);
            acc3.x = fmaf(a3.w, wv3.x, acc3.x); acc3.y = fmaf(a3.w, wv3.y, acc3.y);
        }

        const float2 accs[BATCH] = {acc0, acc1, acc2, acc3};
#pragma unroll
        for (int q = 0; q < BATCH; ++q) {
            const int v = base + q;
            if (v < N) {
                const float2 res =
                    reinterpret_cast<const float2*>(nf)[(size_t)v * 32 + lane];
                float2 o;
                o.x = fmaxf(accs[q].x + bb.x, 0.f) + res.x;
                o.y = fmaxf(accs[q].y + bb.y, 0.f) + res.y;
                reinterpret_cast<float2*>(out)[(size_t)v * 32 + lane] = o;
            }
        }
        __syncwarp();
        base = nxt;
    }
}

// ---------------------------------------------------------------------------
// Input order: node_feats, edge_feats, src, dst, W, b
// ---------------------------------------------------------------------------
extern "C" void kernel_launch(void* const* d_in, const int* in_sizes, int n_in,
                              void* d_out, int out_size) {
    const float* nf  = (const float*)d_in[0];
    const float* ef  = (const float*)d_in[1];
    const int*   src = (const int*)  d_in[2];
    const int*   dst = (const int*)  d_in[3];
    const float* W   = (const float*)d_in[4];
    const float* b   = (const float*)d_in[5];
    float* out = (float*)d_out;

    const int N = in_sizes[0] / DIM;
    const int E = in_sizes[2];

    const int prep_threads = (E + 3) / 4;
    prep_kernel<<<(prep_threads + 255) / 256, 256>>>(dst, W, E, N);
    // persistent + ticketed: grid = resident capacity at 3 blocks/SM
    fused_kernel<<<148 * 3, WARPS * 32>>>(
        (const float4*)nf, (const float4*)ef, src, nf, b, out, N);
}

// round 17
// speedup vs baseline: 1.2169x; 1.1653x over previous
#include <cuda_runtime.h>
#include <math.h>
#include <stdint.h>

#define DIM   64
#define WARPS 8
#define BATCH 4
#define MAXN  65537
#define FULL  0xffffffffu

// packed {log2(e), log2(e)}
#define L2E2  0x3FB8AA3B3FB8AA3Bull

// Scratch (device globals — no allocations allowed)
__device__ int   g_row_ptr[MAXN + 1];
__device__ float g_Wt[DIM * DIM];   // Wt[k*64 + j] = W[j*64 + k]
__device__ int   g_ctr;

// ---------------------------------------------------------------------------
// Prep: W transpose + CSR row_ptr from SORTED dst (int4 loads) + ticket reset.
// ---------------------------------------------------------------------------
__global__ void prep_kernel(const int* __restrict__ dst,
                            const float* __restrict__ W, int E, int N) {
    const int t = blockIdx.x * blockDim.x + threadIdx.x;
    if (t == 0) g_ctr = 0;
    if (t < DIM * DIM) {
        const int j = t & (DIM - 1);
        const int k = t >> 6;
        g_Wt[t] = W[j * DIM + k];
    }
    const int e4 = t * 4;
    if (e4 >= E) return;
    if (e4 + 3 < E) {
        const int4 d = reinterpret_cast<const int4*>(dst)[t];
        const int dm1 = (e4 == 0) ? -1 : __ldg(&dst[e4 - 1]);
        for (int j = dm1 + 1;  j <= d.x; ++j) g_row_ptr[j] = e4;
        for (int j = d.x + 1;  j <= d.y; ++j) g_row_ptr[j] = e4 + 1;
        for (int j = d.y + 1;  j <= d.z; ++j) g_row_ptr[j] = e4 + 2;
        for (int j = d.z + 1;  j <= d.w; ++j) g_row_ptr[j] = e4 + 3;
        if (e4 + 4 >= E)
            for (int j = d.w + 1; j <= N; ++j) g_row_ptr[j] = E;
    } else {
        for (int e = e4; e < E; ++e) {
            const int d     = dst[e];
            const int dprev = (e == 0) ? -1 : dst[e - 1];
            for (int j = dprev + 1; j <= d; ++j) g_row_ptr[j] = e;
            if (e == E - 1)
                for (int j = d + 1; j <= N; ++j) g_row_ptr[j] = E;
        }
    }
}

// ---------------------------------------------------------------------------
// Fused kernel v11 — R13 (best: 64.0us) + MASKED-TAIL windows.
//
// R14/R15 falsified "in-flight = warps x window": window 6 and 12 both lost
// to 8 because mean degree 16 is a multiple of 8 — the 2-edge remainder path
// (2 loads in flight, ~3x slower/edge) is what made them lose. So: remove
// the remainder path. The last partial 8-group of each node runs the SAME
// full-width window with edge indices clamped to cnt-1 and a per-edge
// {0,1} weight folded into the exp (masked edges contribute exactly 0 to
// s and ws). Clamped loads are cache-hot; ~21% fake edge math is the price
// for running 100% of edges at 8-in-flight pace.
//
// Everything else identical to R13: warp-per-node ticketed BATCH=4,
// coalesced warp-wide src chunk + shfl, ef streamed via __ldcs, packed
// f32x2 edge math, softmax without max-shift (m ~ N(0,2), |m| < ~9 over
// 5e7 samples -> exp < 8.2e3; shift cancels exactly), __fdividef
// normalize, BATCH-amortized MLP, 4 blocks/SM.
// ---------------------------------------------------------------------------
__global__ void __launch_bounds__(WARPS * 32, 4)
fused_kernel(const float4* __restrict__ nf4,
             const float4* __restrict__ ef4,
             const int*    __restrict__ src,
             const float*  __restrict__ nf,
             const float*  __restrict__ bias,
             float*        __restrict__ out,
             int N) {
    const int w    = threadIdx.x >> 5;
    const int lane = threadIdx.x & 31;
    const int half = lane >> 4;
    const int l4   = lane & 15;

    __shared__ float4 s_agg[WARPS][BATCH][16];   // 8KB

    const float2* __restrict__ Wt2 = reinterpret_cast<const float2*>(g_Wt);
    const float2  bb = reinterpret_cast<const float2*>(bias)[lane];

    int t = 0;
    if (lane == 0) t = atomicAdd(&g_ctr, BATCH);
    int base = __shfl_sync(FULL, t, 0);

    while (base < N) {
        if (lane == 0) t = atomicAdd(&g_ctr, BATCH);   // prefetch next ticket
        const int nxt = __shfl_sync(FULL, t, 0);

        // ---- Phase A: aggregate BATCH nodes ----
        for (int q = 0; q < BATCH; ++q) {
            const int v = base + q;
            int lo = 0, hi = 0;
            if (v < N) { lo = g_row_ptr[v]; hi = g_row_ptr[v + 1]; }

            // packed accumulators: {s0,s1},{s2,s3},{ws0,ws1},{ws2,ws3}
            uint64_t s01 = 0ull, s23 = 0ull, ws01 = 0ull, ws23 = 0ull;

// packed-f32x2 edge math (R13): 2 ADD2 + 2 MUL2 + 4 EX2 + 2 ADD2 + 2 FMA2.
// WGT: 1.0f for real edges, 0.0f for clamped fake edges (folded into e).
#define EDGE_MATH_W(a, b, WGT) do {                                            \
    uint64_t a01, a23, b01, b23, m01, m23, t01, t23, e01, e23;                 \
    asm("mov.b64 %0, {%1,%2};" : "=l"(a01) : "f"((a).x), "f"((a).y));          \
    asm("mov.b64 %0, {%1,%2};" : "=l"(a23) : "f"((a).z), "f"((a).w));          \
    asm("mov.b64 %0, {%1,%2};" : "=l"(b01) : "f"((b).x), "f"((b).y));          \
    asm("mov.b64 %0, {%1,%2};" : "=l"(b23) : "f"((b).z), "f"((b).w));          \
    asm("add.rn.f32x2 %0, %1, %2;" : "=l"(m01) : "l"(a01), "l"(b01));          \
    asm("add.rn.f32x2 %0, %1, %2;" : "=l"(m23) : "l"(a23), "l"(b23));          \
    asm("mul.rn.f32x2 %0, %1, %2;" : "=l"(t01) : "l"(m01), "l"(L2E2));         \
    asm("mul.rn.f32x2 %0, %1, %2;" : "=l"(t23) : "l"(m23), "l"(L2E2));         \
    float t0, t1, t2, t3, e0, e1, e2, e3;                                      \
    asm("mov.b64 {%0,%1}, %2;" : "=f"(t0), "=f"(t1) : "l"(t01));               \
    asm("mov.b64 {%0,%1}, %2;" : "=f"(t2), "=f"(t3) : "l"(t23));               \
    asm("ex2.approx.f32 %0, %1;" : "=f"(e0) : "f"(t0));                        \
    asm("ex2.approx.f32 %0, %1;" : "=f"(e1) : "f"(t1));                        \
    asm("ex2.approx.f32 %0, %1;" : "=f"(e2) : "f"(t2));                        \
    asm("ex2.approx.f32 %0, %1;" : "=f"(e3) : "f"(t3));                        \
    e0 *= (WGT); e1 *= (WGT); e2 *= (WGT); e3 *= (WGT);                        \
    asm("mov.b64 %0, {%1,%2};" : "=l"(e01) : "f"(e0), "f"(e1));                \
    asm("mov.b64 %0, {%1,%2};" : "=l"(e23) : "f"(e2), "f"(e3));                \
    asm("add.rn.f32x2 %0, %0, %1;" : "+l"(s01) : "l"(e01));                    \
    asm("add.rn.f32x2 %0, %0, %1;" : "+l"(s23) : "l"(e23));                    \
    asm("fma.rn.f32x2 %0, %1, %2, %0;" : "+l"(ws01) : "l"(m01), "l"(e01));     \
    asm("fma.rn.f32x2 %0, %1, %2, %0;" : "+l"(ws23) : "l"(m23), "l"(e23));     \
} while (0)
#define EDGE_MATH(a, b) do {                                                   \
    uint64_t a01, a23, b01, b23, m01, m23, t01, t23, e01, e23;                 \
    asm("mov.b64 %0, {%1,%2};" : "=l"(a01) : "f"((a).x), "f"((a).y));          \
    asm("mov.b64 %0, {%1,%2};" : "=l"(a23) : "f"((a).z), "f"((a).w));          \
    asm("mov.b64 %0, {%1,%2};" : "=l"(b01) : "f"((b).x), "f"((b).y));          \
    asm("mov.b64 %0, {%1,%2};" : "=l"(b23) : "f"((b).z), "f"((b).w));          \
    asm("add.rn.f32x2 %0, %1, %2;" : "=l"(m01) : "l"(a01), "l"(b01));          \
    asm("add.rn.f32x2 %0, %1, %2;" : "=l"(m23) : "l"(a23), "l"(b23));          \
    asm("mul.rn.f32x2 %0, %1, %2;" : "=l"(t01) : "l"(m01), "l"(L2E2));         \
    asm("mul.rn.f32x2 %0, %1, %2;" : "=l"(t23) : "l"(m23), "l"(L2E2));         \
    float t0, t1, t2, t3, e0, e1, e2, e3;                                      \
    asm("mov.b64 {%0,%1}, %2;" : "=f"(t0), "=f"(t1) : "l"(t01));               \
    asm("mov.b64 {%0,%1}, %2;" : "=f"(t2), "=f"(t3) : "l"(t23));               \
    asm("ex2.approx.f32 %0, %1;" : "=f"(e0) : "f"(t0));                        \
    asm("ex2.approx.f32 %0, %1;" : "=f"(e1) : "f"(t1));                        \
    asm("ex2.approx.f32 %0, %1;" : "=f"(e2) : "f"(t2));                        \
    asm("ex2.approx.f32 %0, %1;" : "=f"(e3) : "f"(t3));                        \
    asm("mov.b64 %0, {%1,%2};" : "=l"(e01) : "f"(e0), "f"(e1));                \
    asm("mov.b64 %0, {%1,%2};" : "=l"(e23) : "f"(e2), "f"(e3));                \
    asm("add.rn.f32x2 %0, %0, %1;" : "+l"(s01) : "l"(e01));                    \
    asm("add.rn.f32x2 %0, %0, %1;" : "+l"(s23) : "l"(e23));                    \
    asm("fma.rn.f32x2 %0, %1, %2, %0;" : "+l"(ws01) : "l"(m01), "l"(e01));     \
    asm("fma.rn.f32x2 %0, %1, %2, %0;" : "+l"(ws23) : "l"(m23), "l"(e23));     \
} while (0)

            for (int cb = lo; cb < hi; cb += 32) {
                const int cnt = min(32, hi - cb);
                const int su = __ldg(&src[cb + min(lane, cnt - 1)]);

                int i = 0;
                for (; i + 8 <= cnt; i += 8) {          // full 8-edge windows
                    const int ib = i + 4 * half;
                    const int u0 = __shfl_sync(FULL, su, ib + 0);
                    const int u1 = __shfl_sync(FULL, su, ib + 1);
                    const int u2 = __shfl_sync(FULL, su, ib + 2);
                    const int u3 = __shfl_sync(FULL, su, ib + 3);
                    const unsigned eb = (unsigned)(cb + ib) * 16u + l4;
                    const float4 a0 = __ldg (&nf4[(unsigned)u0 * 16u + l4]);
                    const float4 b0 = __ldcs(&ef4[eb +  0]);
                    const float4 a1 = __ldg (&nf4[(unsigned)u1 * 16u + l4]);
                    const float4 b1 = __ldcs(&ef4[eb + 16]);
                    const float4 a2 = __ldg (&nf4[(unsigned)u2 * 16u + l4]);
                    const float4 b2 = __ldcs(&ef4[eb + 32]);
                    const float4 a3 = __ldg (&nf4[(unsigned)u3 * 16u + l4]);
                    const float4 b3 = __ldcs(&ef4[eb + 48]);
                    EDGE_MATH(a0, b0);
                    EDGE_MATH(a1, b1);
                    EDGE_MATH(a2, b2);
                    EDGE_MATH(a3, b3);
                }
                if (i < cnt) {                          // MASKED full window
                    const int ib = i + 4 * half;
                    // clamped edge indices (reload same lines when past end)
                    const int i0 = min(ib + 0, cnt - 1);
                    const int i1 = min(ib + 1, cnt - 1);
                    const int i2 = min(ib + 2, cnt - 1);
                    const int i3 = min(ib + 3, cnt - 1);
                    const int u0 = __shfl_sync(FULL, su, i0);
                    const int u1 = __shfl_sync(FULL, su, i1);
                    const int u2 = __shfl_sync(FULL, su, i2);
                    const int u3 = __shfl_sync(FULL, su, i3);
                    const float4 a0 = __ldg (&nf4[(unsigned)u0 * 16u + l4]);
                    const float4 b0 = __ldcs(&ef4[(unsigned)(cb + i0) * 16u + l4]);
                    const float4 a1 = __ldg (&nf4[(unsigned)u1 * 16u + l4]);
                    const float4 b1 = __ldcs(&ef4[(unsigned)(cb + i1) * 16u + l4]);
                    const float4 a2 = __ldg (&nf4[(unsigned)u2 * 16u + l4]);
                    const float4 b2 = __ldcs(&ef4[(unsigned)(cb + i2) * 16u + l4]);
                    const float4 a3 = __ldg (&nf4[(unsigned)u3 * 16u + l4]);
                    const float4 b3 = __ldcs(&ef4[(unsigned)(cb + i3) * 16u + l4]);
                    const float w0 = (ib + 0 < cnt) ? 1.f : 0.f;
                    const float w1 = (ib + 1 < cnt) ? 1.f : 0.f;
                    const float w2 = (ib + 2 < cnt) ? 1.f : 0.f;
                    const float w3 = (ib + 3 < cnt) ? 1.f : 0.f;
                    EDGE_MATH_W(a0, b0, w0);
                    EDGE_MATH_W(a1, b1, w1);
                    EDGE_MATH_W(a2, b2, w2);
                    EDGE_MATH_W(a3, b3, w3);
                }
            }
#undef EDGE_MATH
#undef EDGE_MATH_W

            // unpack accumulators, combine half-warps
            float4 s, ws;
            asm("mov.b64 {%0,%1}, %2;" : "=f"(s.x),  "=f"(s.y)  : "l"(s01));
            asm("mov.b64 {%0,%1}, %2;" : "=f"(s.z),  "=f"(s.w)  : "l"(s23));
            asm("mov.b64 {%0,%1}, %2;" : "=f"(ws.x), "=f"(ws.y) : "l"(ws01));
            asm("mov.b64 {%0,%1}, %2;" : "=f"(ws.z), "=f"(ws.w) : "l"(ws23));

            s.x  += __shfl_down_sync(FULL, s.x,  16);
            s.y  += __shfl_down_sync(FULL, s.y,  16);
            s.z  += __shfl_down_sync(FULL, s.z,  16);
            s.w  += __shfl_down_sync(FULL, s.w,  16);
            ws.x += __shfl_down_sync(FULL, ws.x, 16);
            ws.y += __shfl_down_sync(FULL, ws.y, 16);
            ws.z += __shfl_down_sync(FULL, ws.z, 16);
            ws.w += __shfl_down_sync(FULL, ws.w, 16);

            if (half == 0) {
                float4 agg = make_float4(0.f, 0.f, 0.f, 0.f);
                if (hi > lo) {
                    agg.x = __fdividef(ws.x, fmaxf(s.x, 1e-38f));
                    agg.y = __fdividef(ws.y, fmaxf(s.y, 1e-38f));
                    agg.z = __fdividef(ws.z, fmaxf(s.z, 1e-38f));
                    agg.w = __fdividef(ws.w, fmaxf(s.w, 1e-38f));
                }
                s_agg[w][q][l4] = agg;
            }
        }
        __syncwarp();

        // ---- Phase B: one MLP pass for BATCH nodes (W amortized 4x) ----
        float2 acc0 = make_float2(0.f, 0.f), acc1 = make_float2(0.f, 0.f);
        float2 acc2 = make_float2(0.f, 0.f), acc3 = make_float2(0.f, 0.f);
        for (int k4 = 0; k4 < 16; ++k4) {
            const float2 wv0 = Wt2[(4 * k4 + 0) * 32 + lane];
            const float2 wv1 = Wt2[(4 * k4 + 1) * 32 + lane];
            const float2 wv2 = Wt2[(4 * k4 + 2) * 32 + lane];
            const float2 wv3 = Wt2[(4 * k4 + 3) * 32 + lane];
            const float4 a0 = s_agg[w][0][k4];   // broadcast LDS.128
            const float4 a1 = s_agg[w][1][k4];
            const float4 a2 = s_agg[w][2][k4];
            const float4 a3 = s_agg[w][3][k4];
            acc0.x = fmaf(a0.x, wv0.x, acc0.x); acc0.y = fmaf(a0.x, wv0.y, acc0.y);
            acc0.x = fmaf(a0.y, wv1.x, acc0.x); acc0.y = fmaf(a0.y, wv1.y, acc0.y);
            acc0.x = fmaf(a0.z, wv2.x, acc0.x); acc0.y = fmaf(a0.z, wv2.y, acc0.y);
            acc0.x = fmaf(a0.w, wv3.x, acc0.x); acc0.y = fmaf(a0.w, wv3.y, acc0.y);
            acc1.x = fmaf(a1.x, wv0.x, acc1.x); acc1.y = fmaf(a1.x, wv0.y, acc1.y);
            acc1.x = fmaf(a1.y, wv1.x, acc1.x); acc1.y = fmaf(a1.y, wv1.y, acc1.y);
            acc1.x = fmaf(a1.z, wv2.x, acc1.x); acc1.y = fmaf(a1.z, wv2.y, acc1.y);
            acc1.x = fmaf(a1.w, wv3.x, acc1.x); acc1.y = fmaf(a1.w, wv3.y, acc1.y);
            acc2.x = fmaf(a2.x, wv0.x, acc2.x); acc2.y = fmaf(a2.x, wv0.y, acc2.y);
            acc2.x = fmaf(a2.y, wv1.x, acc2.x); acc2.y = fmaf(a2.y, wv1.y, acc2.y);
            acc2.x = fmaf(a2.z, wv2.x, acc2.x); acc2.y = fmaf(a2.z, wv2.y, acc2.y);
            acc2.x = fmaf(a2.w, wv3.x, acc2.x); acc2.y = fmaf(a2.w, wv3.y, acc2.y);
            acc3.x = fmaf(a3.x, wv0.x, acc3.x); acc3.y = fmaf(a3.x, wv0.y, acc3.y);
            acc3.x = fmaf(a3.y, wv1.x, acc3.x); acc3.y = fmaf(a3.y, wv1.y, acc3.y);
            acc3.x = fmaf(a3.z, wv2.x, acc3.x); acc3.y = fmaf(a3.z, wv2.y, acc3.y);
            acc3.x = fmaf(a3.w, wv3.x, acc3.x); acc3.y = fmaf(a3.w, wv3.y, acc3.y);
        }

        const float2 accs[BATCH] = {acc0, acc1, acc2, acc3};
#pragma unroll
        for (int q = 0; q < BATCH; ++q) {
            const int v = base + q;
            if (v < N) {
                const float2 res =
                    reinterpret_cast<const float2*>(nf)[(size_t)v * 32 + lane];
                float2 o;
                o.x = fmaxf(accs[q].x + bb.x, 0.f) + res.x;
                o.y = fmaxf(accs[q].y + bb.y, 0.f) + res.y;
                reinterpret_cast<float2*>(out)[(size_t)v * 32 + lane] = o;
            }
        }
        __syncwarp();
        base = nxt;
    }
}

// ---------------------------------------------------------------------------
// Input order: node_feats, edge_feats, src, dst, W, b
// ---------------------------------------------------------------------------
extern "C" void kernel_launch(void* const* d_in, const int* in_sizes, int n_in,
                              void* d_out, int out_size) {
    const float* nf  = (const float*)d_in[0];
    const float* ef  = (const float*)d_in[1];
    const int*   src = (const int*)  d_in[2];
    const int*   dst = (const int*)  d_in[3];
    const float* W   = (const float*)d_in[4];
    const float* b   = (const float*)d_in[5];
    float* out = (float*)d_out;

    const int N = in_sizes[0] / DIM;
    const int E = in_sizes[2];

    const int prep_threads = (E + 3) / 4;
    prep_kernel<<<(prep_threads + 255) / 256, 256>>>(dst, W, E, N);
    fused_kernel<<<148 * 8, WARPS * 32>>>(
        (const float4*)nf, (const float4*)ef, src, nf, b, out, N);
}